// round 3
// baseline (speedup 1.0000x reference)
#include <cuda_runtime.h>
#include <cuda_fp16.h>
#include <math.h>
#include <stdint.h>

// ============================================================================
// Decoder_33208687133135 on GB300 (sm_103a) — Round 2
//
// Full-M formulation: M = 262144 rows = [s-MLP 131072 | t-MLP 131072].
// z row r (r<131072): Z[r][l] = koopman[r>>6][l][r&63]
// H1 = tanh(Z@W1+b1); H2 = tanh(H1@W2+b2); H3 = tanh(H2@W3+b3)
// ds[r] = H3_s[r] . sW4[:, r&63] + sb4 ; dt likewise from H3_t
// out = (x - dt) * exp(-ds)
//
// Precision: split-fp16 (hi+lo), 3 MMA products (AhBh + AhBl + AlBh), fp32 acc.
// GEMM: 128x64 CTA tile, BK=64, cp.async double buffer, ldmatrix.x4, mma.16816.
// ============================================================================

#define MTOT   262144            // 2 * 131072
#define HALF_M 131072
#define NDIM   512

// per-MLP transposed-weight layout (halves): W1t 512x64, W2t 512x512, W3t 512x512
#define OFF_W1 0
#define OFF_W2 32768
#define OFF_W3 294912
#define MLP_STRIDE 557056

// -------- static device scratch ---------------------------------------------
__device__ __half g_b0h[(size_t)MTOT * NDIM];
__device__ __half g_b0l[(size_t)MTOT * NDIM];
__device__ __half g_b1h[(size_t)MTOT * NDIM];
__device__ __half g_b1l[(size_t)MTOT * NDIM];
__device__ __half g_wh[2 * MLP_STRIDE];
__device__ __half g_wl[2 * MLP_STRIDE];
__device__ float  g_w4t[2 * 64 * 512];   // transposed W4: [i][k], s then t

// -------- PTX helpers --------------------------------------------------------
#define CP16(d, s) asm volatile("cp.async.cg.shared.global [%0], [%1], 16;" :: "r"(d), "l"(s))
#define CP_COMMIT  asm volatile("cp.async.commit_group;")
#define CP_WAIT(n) asm volatile("cp.async.wait_group %0;" :: "n"(n))

#define LDSM4(R, addr)                                                         \
    asm volatile("ldmatrix.sync.aligned.m8n8.x4.shared.b16 {%0,%1,%2,%3}, [%4];" \
        : "=r"(R[0]), "=r"(R[1]), "=r"(R[2]), "=r"(R[3]) : "r"(addr))

#define MMA(d, a, b0, b1)                                                      \
    asm volatile("mma.sync.aligned.m16n8k16.row.col.f32.f16.f16.f32 "          \
        "{%0,%1,%2,%3},{%4,%5,%6,%7},{%8,%9},{%0,%1,%2,%3};"                   \
        : "+f"(d[0]), "+f"(d[1]), "+f"(d[2]), "+f"(d[3])                       \
        : "r"(a[0]), "r"(a[1]), "r"(a[2]), "r"(a[3]), "r"(b0), "r"(b1))

// smem stage layout (bytes): Ah[128][72] @0, Al @18432, Bh[64][72] @36864, Bl @46080
#define STAGE_BYTES 55296
#define AL_OFF 18432
#define BH_OFF 36864
#define BL_REL 9216

// ---------------------------------------------------------------------------
// weight prep: transpose K x 512(or 64) fp32 -> [n][k] hi/lo fp16 (or fp32)
__device__ __forceinline__ void transpose_split_tile(
    const float* __restrict__ W, int K, int N,
    __half* __restrict__ Wth, __half* __restrict__ Wtl)
{
    __shared__ float t[32][33];
    int tx = threadIdx.x, ty = threadIdx.y;
    int k0 = blockIdx.x * 32, n0 = blockIdx.y * 32;
#pragma unroll
    for (int j = 0; j < 4; j++)
        t[ty + j * 8][tx] = W[(size_t)(k0 + ty + j * 8) * N + n0 + tx];
    __syncthreads();
#pragma unroll
    for (int j = 0; j < 4; j++) {
        int n = n0 + ty + j * 8;
        float v = t[tx][ty + j * 8];
        __half h = __float2half_rn(v);
        size_t o = (size_t)n * K + k0 + tx;
        Wth[o] = h;
        Wtl[o] = __float2half_rn(v - __half2float(h));
    }
}

__device__ __forceinline__ void transpose_f32_tile(
    const float* __restrict__ W, int K, int N, float* __restrict__ Wt)
{
    __shared__ float t2[32][33];
    int tx = threadIdx.x, ty = threadIdx.y;
    int k0 = blockIdx.x * 32, n0 = blockIdx.y * 32;
#pragma unroll
    for (int j = 0; j < 4; j++)
        t2[ty + j * 8][tx] = W[(size_t)(k0 + ty + j * 8) * N + n0 + tx];
    __syncthreads();
#pragma unroll
    for (int j = 0; j < 4; j++) {
        int n = n0 + ty + j * 8;
        Wt[(size_t)n * K + k0 + tx] = t2[tx][ty + j * 8];
    }
}

__global__ void prep_a(const float* sW1, const float* tW1,
                       const float* sW4, const float* tW4,
                       __half* wh, __half* wl, float* w4t)
{
    int z = blockIdx.z;
    if (z == 0)      { if (blockIdx.x < 2) transpose_split_tile(sW1, 64, 512, wh + OFF_W1, wl + OFF_W1); }
    else if (z == 1) { if (blockIdx.x < 2) transpose_split_tile(tW1, 64, 512, wh + MLP_STRIDE + OFF_W1, wl + MLP_STRIDE + OFF_W1); }
    else if (z == 2) { if (blockIdx.y < 2) transpose_f32_tile(sW4, 512, 64, w4t); }
    else             { if (blockIdx.y < 2) transpose_f32_tile(tW4, 512, 64, w4t + 32768); }
}

__global__ void prep_w23(const float* W2, const float* W3, __half* wh, __half* wl)
{
    if (blockIdx.z == 0) transpose_split_tile(W2, 512, 512, wh + OFF_W2, wl + OFF_W2);
    else                 transpose_split_tile(W3, 512, 512, wh + OFF_W3, wl + OFF_W3);
}

// ---------------------------------------------------------------------------
__device__ __forceinline__ void epilogue_store(
    float (&acc)[2][4][4], const float* __restrict__ bias,
    __half* __restrict__ Oh, __half* __restrict__ Ol,
    int m0, int n0, int wm, int wn, int grp, int q)
{
#pragma unroll
    for (int mi = 0; mi < 2; ++mi)
#pragma unroll
    for (int nj = 0; nj < 4; ++nj) {
        int row = m0 + wm * 32 + mi * 16 + grp;
        int col = n0 + wn * 32 + nj * 8 + q * 2;
        float bb0 = bias[col], bb1 = bias[col + 1];
        float v00 = tanhf(acc[mi][nj][0] + bb0);
        float v01 = tanhf(acc[mi][nj][1] + bb1);
        float v10 = tanhf(acc[mi][nj][2] + bb0);
        float v11 = tanhf(acc[mi][nj][3] + bb1);
        __half h00 = __float2half_rn(v00), h01 = __float2half_rn(v01);
        __half h10 = __float2half_rn(v10), h11 = __float2half_rn(v11);
        __half l00 = __float2half_rn(v00 - __half2float(h00));
        __half l01 = __float2half_rn(v01 - __half2float(h01));
        __half l10 = __float2half_rn(v10 - __half2float(h10));
        __half l11 = __float2half_rn(v11 - __half2float(h11));
        size_t o0 = (size_t)row * NDIM + col;
        size_t o1 = o0 + (size_t)8 * NDIM;
        *reinterpret_cast<__half2*>(Oh + o0) = __halves2half2(h00, h01);
        *reinterpret_cast<__half2*>(Oh + o1) = __halves2half2(h10, h11);
        *reinterpret_cast<__half2*>(Ol + o0) = __halves2half2(l00, l01);
        *reinterpret_cast<__half2*>(Ol + o1) = __halves2half2(l10, l11);
    }
}

// shared compute of one 64-deep k stage from smem buffer at byte base `cur`
__device__ __forceinline__ void compute_stage(
    uint32_t cur, const uint32_t offA[2], const uint32_t offB[2],
    float (&acc)[2][4][4])
{
#pragma unroll
    for (int ks = 0; ks < 64; ks += 16) {
        uint32_t ah[2][4], al_[2][4];
#pragma unroll
        for (int mi = 0; mi < 2; ++mi) {
            LDSM4(ah[mi],  cur + offA[mi] + ks * 2);
            LDSM4(al_[mi], cur + AL_OFF + offA[mi] + ks * 2);
        }
#pragma unroll
        for (int nj2 = 0; nj2 < 2; ++nj2) {
            uint32_t bh[4], bl[4];
            LDSM4(bh, cur + offB[nj2] + ks * 2);
            LDSM4(bl, cur + BL_REL + offB[nj2] + ks * 2);
#pragma unroll
            for (int mi = 0; mi < 2; ++mi) {
                MMA(acc[mi][nj2 * 2],     ah[mi],  bh[0], bh[1]);
                MMA(acc[mi][nj2 * 2],     ah[mi],  bl[0], bl[1]);
                MMA(acc[mi][nj2 * 2],     al_[mi], bh[0], bh[1]);
                MMA(acc[mi][nj2 * 2 + 1], ah[mi],  bh[2], bh[3]);
                MMA(acc[mi][nj2 * 2 + 1], ah[mi],  bl[2], bl[3]);
                MMA(acc[mi][nj2 * 2 + 1], al_[mi], bh[2], bh[3]);
            }
        }
    }
}

// ---------------------------------------------------------------------------
// K=512 GEMM with cp.async double buffering. O = split(tanh(A@Wt^T + b)).
__global__ __launch_bounds__(256) void gemm512_kernel(
    const __half* __restrict__ Ah, const __half* __restrict__ Al,
    const __half* __restrict__ WhS, const __half* __restrict__ WlS,
    const __half* __restrict__ WhT, const __half* __restrict__ WlT,
    const float* __restrict__ biasS, const float* __restrict__ biasT,
    __half* __restrict__ Oh, __half* __restrict__ Ol)
{
    extern __shared__ __half sm[];
    uint32_t sb = (uint32_t)__cvta_generic_to_shared(sm);
    const int tid = threadIdx.x, lane = tid & 31, wid = tid >> 5;
    const int wm = wid & 3, wn = wid >> 2, grp = lane >> 2, q = lane & 3;
    const int m0 = blockIdx.y * 128, n0 = blockIdx.x * 64;
    const bool isS = blockIdx.y < (gridDim.y >> 1);
    const __half* Wh = isS ? WhS : WhT;
    const __half* Wl = isS ? WlS : WlT;
    const float* bias = isS ? biasS : biasT;

    float acc[2][4][4];
#pragma unroll
    for (int a = 0; a < 2; a++)
#pragma unroll
        for (int b = 0; b < 4; b++)
#pragma unroll
            for (int c = 0; c < 4; c++) acc[a][b][c] = 0.0f;

    uint32_t offA[2], offB[2];
#pragma unroll
    for (int mi = 0; mi < 2; ++mi)
        offA[mi] = ((wm * 32 + mi * 16 + (lane & 15)) * 72 + (lane >> 4) * 8) * 2;
#pragma unroll
    for (int nj2 = 0; nj2 < 2; ++nj2)
        offB[nj2] = BH_OFF +
            ((wn * 32 + nj2 * 16 + (lane & 7) + ((lane >> 4) << 3)) * 72 +
             ((lane >> 3) & 1) * 8) * 2;

    // stage loader
    auto load_stage = [&](uint32_t base, int k0) {
#pragma unroll
        for (int i = 0; i < 4; i++) {
            int c = tid + i * 256;
            int r = c >> 3, kc = (c & 7) << 3;
            size_t g = (size_t)(m0 + r) * 512 + k0 + kc;
            uint32_t d = base + (r * 72 + kc) * 2;
            CP16(d, Ah + g);
            CP16(d + AL_OFF, Al + g);
        }
#pragma unroll
        for (int i = 0; i < 2; i++) {
            int c = tid + i * 256;
            int n = c >> 3, kc = (c & 7) << 3;
            size_t g = (size_t)(n0 + n) * 512 + k0 + kc;
            uint32_t d = base + BH_OFF + (n * 72 + kc) * 2;
            CP16(d, Wh + g);
            CP16(d + BL_REL, Wl + g);
        }
    };

    load_stage(sb, 0);
    CP_COMMIT;
    for (int it = 0; it < 8; ++it) {
        uint32_t cur = sb + (it & 1) * STAGE_BYTES;
        if (it < 7) {
            load_stage(sb + ((it + 1) & 1) * STAGE_BYTES, (it + 1) * 64);
            CP_COMMIT;
            CP_WAIT(1);
        } else {
            CP_WAIT(0);
        }
        __syncthreads();
        compute_stage(cur, offA, offB, acc);
        __syncthreads();
    }
    epilogue_store(acc, bias, Oh, Ol, m0, n0, wm, wn, grp, q);
}

// ---------------------------------------------------------------------------
// Layer-1 GEMM: A built on the fly from koopman (transpose + split), K=64.
__global__ __launch_bounds__(256) void gemm_l1_kernel(
    const float* __restrict__ koop,
    const __half* __restrict__ WhS, const __half* __restrict__ WlS,
    const __half* __restrict__ WhT, const __half* __restrict__ WlT,
    const float* __restrict__ biasS, const float* __restrict__ biasT,
    __half* __restrict__ Oh, __half* __restrict__ Ol)
{
    extern __shared__ __half sm[];
    uint32_t sb = (uint32_t)__cvta_generic_to_shared(sm);
    const int tid = threadIdx.x, lane = tid & 31, wid = tid >> 5;
    const int wm = wid & 3, wn = wid >> 2, grp = lane >> 2, q = lane & 3;
    const int m0 = blockIdx.y * 128, n0 = blockIdx.x * 64;
    const bool isS = blockIdx.y < (gridDim.y >> 1);
    const __half* Wh = isS ? WhS : WhT;
    const __half* Wl = isS ? WlS : WlT;
    const float* bias = isS ? biasS : biasT;

    // B tile (64 n x 64 k) via cp.async; W1t stride = 64
#pragma unroll
    for (int i = 0; i < 2; i++) {
        int c = tid + i * 256;
        int n = c >> 3, kc = (c & 7) << 3;
        size_t g = (size_t)(n0 + n) * 64 + kc;
        uint32_t d = sb + BH_OFF + (n * 72 + kc) * 2;
        CP16(d, Wh + g);
        CP16(d + BL_REL, Wl + g);
    }
    CP_COMMIT;

    // A tile (128 rows x 64 l) from koopman, transposed + split on the fly
#pragma unroll
    for (int i = 0; i < 32; i++) {
        int c = tid + i * 256;
        int rloc = c & 127, l = c >> 7;
        int zr = (m0 + rloc) & (HALF_M - 1);
        float v = koop[(size_t)(zr >> 6) * 4096 + l * 64 + (zr & 63)];
        __half h = __float2half_rn(v);
        sm[rloc * 72 + l] = h;
        sm[9216 + rloc * 72 + l] = __float2half_rn(v - __half2float(h));
    }
    CP_WAIT(0);
    __syncthreads();

    float acc[2][4][4];
#pragma unroll
    for (int a = 0; a < 2; a++)
#pragma unroll
        for (int b = 0; b < 4; b++)
#pragma unroll
            for (int c = 0; c < 4; c++) acc[a][b][c] = 0.0f;

    uint32_t offA[2], offB[2];
#pragma unroll
    for (int mi = 0; mi < 2; ++mi)
        offA[mi] = ((wm * 32 + mi * 16 + (lane & 15)) * 72 + (lane >> 4) * 8) * 2;
#pragma unroll
    for (int nj2 = 0; nj2 < 2; ++nj2)
        offB[nj2] = BH_OFF +
            ((wn * 32 + nj2 * 16 + (lane & 7) + ((lane >> 4) << 3)) * 72 +
             ((lane >> 3) & 1) * 8) * 2;

    compute_stage(sb, offA, offB, acc);
    epilogue_store(acc, bias, Oh, Ol, m0, n0, wm, wn, grp, q);
}

// ---------------------------------------------------------------------------
// final: ds/dt diagonals from H3 halves + output. One warp per output row.
__global__ __launch_bounds__(256) void final_kernel(
    const __half* __restrict__ Hh, const __half* __restrict__ Hl,
    const float* __restrict__ w4t,
    const float* __restrict__ sb4, const float* __restrict__ tb4,
    const float* __restrict__ x, float* __restrict__ out)
{
    const int wid = threadIdx.x >> 5, lane = threadIdx.x & 31;
    const int r = blockIdx.x * 8 + wid;
    const int i = r & 63;
    const __half* psh = Hh + (size_t)r * NDIM;
    const __half* psl = Hl + (size_t)r * NDIM;
    const __half* pth = Hh + (size_t)(r + HALF_M) * NDIM;
    const __half* ptl = Hl + (size_t)(r + HALF_M) * NDIM;
    const float* ws = w4t + i * 512;
    const float* wt = w4t + 32768 + i * 512;
    float ss = 0.0f, st = 0.0f;
#pragma unroll
    for (int k = lane; k < 512; k += 32) {
        ss += (__half2float(psh[k]) + __half2float(psl[k])) * ws[k];
        st += (__half2float(pth[k]) + __half2float(ptl[k])) * wt[k];
    }
#pragma unroll
    for (int off = 16; off; off >>= 1) {
        ss += __shfl_xor_sync(0xffffffffu, ss, off);
        st += __shfl_xor_sync(0xffffffffu, st, off);
    }
    if (lane == 0) {
        float dt = st + tb4[i];
        float ds = ss + sb4[i];
        out[r] = (x[r] - dt) * expf(-ds);
    }
}

// ---------------------------------------------------------------------------
extern "C" void kernel_launch(void* const* d_in, const int* in_sizes, int n_in,
                              void* d_out, int out_size)
{
    (void)in_sizes; (void)n_in; (void)out_size;

    const float* x    = (const float*)d_in[0];
    const float* koop = (const float*)d_in[1];
    const float* sW1 = (const float*)d_in[2];  const float* sb1 = (const float*)d_in[3];
    const float* sW2 = (const float*)d_in[4];  const float* sb2 = (const float*)d_in[5];
    const float* sW3 = (const float*)d_in[6];  const float* sb3 = (const float*)d_in[7];
    const float* sW4 = (const float*)d_in[8];  const float* sb4 = (const float*)d_in[9];
    const float* tW1 = (const float*)d_in[10]; const float* tb1 = (const float*)d_in[11];
    const float* tW2 = (const float*)d_in[12]; const float* tb2 = (const float*)d_in[13];
    const float* tW3 = (const float*)d_in[14]; const float* tb3 = (const float*)d_in[15];
    const float* tW4 = (const float*)d_in[16]; const float* tb4 = (const float*)d_in[17];
    float* out = (float*)d_out;

    __half *b0h, *b0l, *b1h, *b1l, *wh, *wl;
    float* w4t;
    cudaGetSymbolAddress((void**)&b0h, g_b0h);
    cudaGetSymbolAddress((void**)&b0l, g_b0l);
    cudaGetSymbolAddress((void**)&b1h, g_b1h);
    cudaGetSymbolAddress((void**)&b1l, g_b1l);
    cudaGetSymbolAddress((void**)&wh,  g_wh);
    cudaGetSymbolAddress((void**)&wl,  g_wl);
    cudaGetSymbolAddress((void**)&w4t, g_w4t);

    static int attr_done = 0;
    if (!attr_done) {
        cudaFuncSetAttribute(gemm512_kernel,
                             cudaFuncAttributeMaxDynamicSharedMemorySize, 2 * STAGE_BYTES);
        cudaFuncSetAttribute(gemm_l1_kernel,
                             cudaFuncAttributeMaxDynamicSharedMemorySize, STAGE_BYTES);
        attr_done = 1;
    }

    // weight prep (3 launches)
    prep_a  <<<dim3(16, 16, 4), dim3(32, 8)>>>(sW1, tW1, sW4, tW4, wh, wl, w4t);
    prep_w23<<<dim3(16, 16, 2), dim3(32, 8)>>>(sW2, sW3, wh, wl);
    prep_w23<<<dim3(16, 16, 2), dim3(32, 8)>>>(tW2, tW3, wh + MLP_STRIDE, wl + MLP_STRIDE);

    dim3 grid(8, MTOT / 128);
    // layer 1 (K=64, A from koopman)
    gemm_l1_kernel<<<grid, 256, STAGE_BYTES>>>(
        koop, wh + OFF_W1, wl + OFF_W1, wh + MLP_STRIDE + OFF_W1, wl + MLP_STRIDE + OFF_W1,
        sb1, tb1, b0h, b0l);
    // layer 2
    gemm512_kernel<<<grid, 256, 2 * STAGE_BYTES>>>(
        b0h, b0l, wh + OFF_W2, wl + OFF_W2, wh + MLP_STRIDE + OFF_W2, wl + MLP_STRIDE + OFF_W2,
        sb2, tb2, b1h, b1l);
    // layer 3
    gemm512_kernel<<<grid, 256, 2 * STAGE_BYTES>>>(
        b1h, b1l, wh + OFF_W3, wl + OFF_W3, wh + MLP_STRIDE + OFF_W3, wl + MLP_STRIDE + OFF_W3,
        sb3, tb3, b0h, b0l);
    // diagonal + output
    final_kernel<<<HALF_M / 8, 256>>>(b0h, b0l, w4t, sb4, tb4, x, out);
}

// round 9
// speedup vs baseline: 1.6555x; 1.6555x over previous
#include <cuda_runtime.h>
#include <cuda_fp16.h>
#include <math.h>
#include <stdint.h>

// ============================================================================
// Decoder_33208687133135 — Round 8: R6 design + device-symbol-arg bugfix.
// rows r (per MLP, 131072): Z[r][l] = koopman[r>>6][l][r&63]
// h1=tanh(Z W1+b1); h2=tanh(h1 W2+b2); h3=tanh(h2 W3+b3); diag=h3.W4[:,r&63]
// out = (x - dt) * exp(-ds)
// Weights split hi/lo fp16 (2 products); activations fp16; Z split (3 prod).
// Layer-3 epilogue computes the W4 diagonal directly from fp32 accumulators.
// ============================================================================

#define HALF_M 131072
#define MTOT   262144

// ---- static scratch --------------------------------------------------------
__device__ __half g_zh[(size_t)HALF_M * 64];
__device__ __half g_zl[(size_t)HALF_M * 64];
__device__ __half g_w1h[2][512 * 64];            // [mlp], W1^T [n][k]
__device__ __half g_w1l[2][512 * 64];
__device__ __half g_w23h[4][512 * 512];          // [mlp*2+layer], W^T [n][k]
__device__ __half g_w23l[4][512 * 512];
__device__ float  g_w4t[2][64 * 512];            // [mlp], W4^T [i][k]
__device__ __half g_h1[(size_t)MTOT * 512];
__device__ __half g_h2[(size_t)MTOT * 512];
__device__ float  g_part[16][MTOT];              // diag partials per 32-n slice

// ---- PTX helpers -----------------------------------------------------------
#define CP16(d, s) asm volatile("cp.async.cg.shared.global [%0], [%1], 16;" :: "r"(d), "l"(s))
#define CP_COMMIT  asm volatile("cp.async.commit_group;")
#define CP_WAIT(n) asm volatile("cp.async.wait_group %0;" :: "n"(n) : "memory")

#define LDSM4(R, addr)                                                         \
    asm volatile("ldmatrix.sync.aligned.m8n8.x4.shared.b16 {%0,%1,%2,%3}, [%4];" \
        : "=r"(R[0]), "=r"(R[1]), "=r"(R[2]), "=r"(R[3]) : "r"(addr))

#define MMA(d, a, b0, b1)                                                      \
    asm volatile("mma.sync.aligned.m16n8k16.row.col.f32.f16.f16.f32 "          \
        "{%0,%1,%2,%3},{%4,%5,%6,%7},{%8,%9},{%0,%1,%2,%3};"                   \
        : "+f"(d[0]), "+f"(d[1]), "+f"(d[2]), "+f"(d[3])                       \
        : "r"(a[0]), "r"(a[1]), "r"(a[2]), "r"(a[3]), "r"(b0), "r"(b1))

// ============================================================================
// prep kernels
// ============================================================================
__global__ __launch_bounds__(256) void prep_z(const float* __restrict__ koop)
{
    __shared__ float s[64][65];
    int b = blockIdx.x;
    const float* src = koop + (size_t)b * 4096;
    for (int e = threadIdx.x; e < 4096; e += 256) {
        int l = e >> 6, i = e & 63;
        s[i][l] = src[e];
    }
    __syncthreads();
    for (int e = threadIdx.x; e < 4096; e += 256) {
        int i = e >> 6, l = e & 63;
        float v = s[i][l];
        __half h = __float2half_rn(v);
        size_t o = (size_t)(b * 64 + i) * 64 + l;
        g_zh[o] = h;
        g_zl[o] = __float2half_rn(v - __half2float(h));
    }
}

__device__ __forceinline__ void tsp_tile(const float* __restrict__ W, int K, int N,
                                         __half* __restrict__ oh, __half* __restrict__ ol)
{
    __shared__ float t[32][33];
    int tx = threadIdx.x, ty = threadIdx.y;
    int k0 = blockIdx.x * 32, n0 = blockIdx.y * 32;
#pragma unroll
    for (int j = 0; j < 4; j++)
        t[ty + j * 8][tx] = W[(size_t)(k0 + ty + j * 8) * N + n0 + tx];
    __syncthreads();
#pragma unroll
    for (int j = 0; j < 4; j++) {
        int n = n0 + ty + j * 8;
        float v = t[tx][ty + j * 8];
        __half h = __float2half_rn(v);
        size_t o = (size_t)n * K + k0 + tx;
        oh[o] = h;
        ol[o] = __float2half_rn(v - __half2float(h));
    }
}

__global__ void prep_w1(const float* sW1, const float* tW1)
{
    int mlp = blockIdx.z;
    tsp_tile(mlp ? tW1 : sW1, 64, 512, g_w1h[mlp], g_w1l[mlp]);
}

__global__ void prep_w23(const float* sW2, const float* sW3,
                         const float* tW2, const float* tW3)
{
    int z = blockIdx.z;   // mlp*2 + layer
    const float* W = (z == 0) ? sW2 : (z == 1) ? sW3 : (z == 2) ? tW2 : tW3;
    tsp_tile(W, 512, 512, g_w23h[z], g_w23l[z]);
}

__global__ __launch_bounds__(256) void prep_w4(const float* sW4, const float* tW4)
{
    int e = blockIdx.x * 256 + threadIdx.x;   // 65536
    int mlp = e >> 15, rem = e & 32767;
    int i = rem >> 9, k = rem & 511;
    g_w4t[mlp][i * 512 + k] = (mlp ? tW4 : sW4)[(size_t)k * 64 + i];
}

// ============================================================================
// smem layouts (halves, stride 72)
// gemm23 stage: A[128][72] @0 (18432B), Bh[128][72] @18432, Bl @36864 ; x2
// ============================================================================
#define ST_BYTES 55296
#define B_OFF    18432
#define G23_BIAS (2 * ST_BYTES)
#define G23_SMEM (2 * ST_BYTES + 512)
// gemm_l1: Ah @0, Al @18432, Bh @36864, Bl @55296, bias @73728
#define L1_SMEM  74240

__device__ __forceinline__ void frag_offsets(int lane, int wm, int wn,
                                             uint32_t offA[4], uint32_t offB[2])
{
#pragma unroll
    for (int mi = 0; mi < 4; ++mi)
        offA[mi] = ((wm * 64 + mi * 16 + (lane & 15)) * 72 + (lane >> 4) * 8) * 2;
#pragma unroll
    for (int j = 0; j < 2; ++j)
        offB[j] = B_OFF +
            ((wn * 32 + j * 16 + (lane & 7) + ((lane >> 4) << 3)) * 72 +
             ((lane >> 3) & 1) * 8) * 2;
}

// 2-product compute of one 64-deep stage (acts fp16, weights hi/lo)
__device__ __forceinline__ void compute2(uint32_t cur, const uint32_t offA[4],
                                         const uint32_t offB[2], float (&acc)[4][4][4])
{
#pragma unroll
    for (int ks = 0; ks < 64; ks += 16) {
        uint32_t a[4][4];
#pragma unroll
        for (int mi = 0; mi < 4; ++mi) LDSM4(a[mi], cur + offA[mi] + ks * 2);
#pragma unroll
        for (int j = 0; j < 2; ++j) {
            uint32_t bh[4], bl[4];
            LDSM4(bh, cur + offB[j] + ks * 2);
            LDSM4(bl, cur + B_OFF + offB[j] + ks * 2);
#pragma unroll
            for (int mi = 0; mi < 4; ++mi) {
                MMA(acc[mi][j * 2],     a[mi], bh[0], bh[1]);
                MMA(acc[mi][j * 2],     a[mi], bl[0], bl[1]);
                MMA(acc[mi][j * 2 + 1], a[mi], bh[2], bh[3]);
                MMA(acc[mi][j * 2 + 1], a[mi], bl[2], bl[3]);
            }
        }
    }
}

// ============================================================================
// gemm23: C = tanh(A @ W^T + b). A selected INSIDE the kernel (device symbols
// must not be passed as host-side kernel args). grid (4 nCTA, 2048 mCTA).
// ============================================================================
__global__ __launch_bounds__(256, 2) void gemm23(
    int layer, int is_l3,
    const float* __restrict__ bias_s, const float* __restrict__ bias_t)
{
    extern __shared__ uint8_t smem[];
    const uint32_t sb = (uint32_t)__cvta_generic_to_shared(smem);
    const int tid = threadIdx.x, lane = tid & 31, wid = tid >> 5;
    const int wm = wid >> 2, wn = wid & 3;        // 2 x 4 warps
    const int grp = lane >> 2, q = lane & 3;
    const int n0 = blockIdx.x * 128;
    const int m0 = blockIdx.y * 128;
    const int mlp = (blockIdx.y >= 1024) ? 1 : 0;
    const __half* A  = layer ? g_h2 : g_h1;       // device-side symbol access
    __half* O        = g_h2;                      // used only when !is_l3
    const __half* Wh = g_w23h[mlp * 2 + layer];
    const __half* Wl = g_w23l[mlp * 2 + layer];

    if (tid < 128)
        ((float*)(smem + G23_BIAS))[tid] = (mlp ? bias_t : bias_s)[n0 + tid];

    auto load_stage = [&](uint32_t base, int k0) {
#pragma unroll
        for (int i = 0; i < 4; i++) {
            int c = tid + i * 256;
            int r = c >> 3, kc = (c & 7) << 3;
            CP16(base + (r * 72 + kc) * 2, A + (size_t)(m0 + r) * 512 + k0 + kc);
        }
#pragma unroll
        for (int i = 0; i < 8; i++) {
            int c = tid + i * 256;
            int hl = c >> 10, cc = c & 1023;
            int n = cc >> 3, kc = (cc & 7) << 3;
            const __half* src = hl ? Wl : Wh;
            CP16(base + B_OFF + hl * 18432 + (n * 72 + kc) * 2,
                 src + (size_t)(n0 + n) * 512 + k0 + kc);
        }
        CP_COMMIT;
    };

    float acc[4][4][4];
#pragma unroll
    for (int a = 0; a < 4; a++)
#pragma unroll
        for (int b = 0; b < 4; b++)
#pragma unroll
            for (int c = 0; c < 4; c++) acc[a][b][c] = 0.f;

    uint32_t offA[4], offB[2];
    frag_offsets(lane, wm, wn, offA, offB);

    load_stage(sb, 0);
    for (int s = 0; s < 8; ++s) {
        if (s < 7) { load_stage(sb + ((s + 1) & 1) * ST_BYTES, (s + 1) * 64); CP_WAIT(1); }
        else       { CP_WAIT(0); }
        __syncthreads();
        compute2(sb + (s & 1) * ST_BYTES, offA, offB, acc);
        __syncthreads();
    }

    const float* sbias = (const float*)(smem + G23_BIAS);
    if (!is_l3) {
#pragma unroll
        for (int mi = 0; mi < 4; ++mi)
#pragma unroll
        for (int nj = 0; nj < 4; ++nj) {
            int row = m0 + wm * 64 + mi * 16 + grp;
            int cl  = wn * 32 + nj * 8 + q * 2;
            float b0 = sbias[cl], b1 = sbias[cl + 1];
            float v00 = tanhf(acc[mi][nj][0] + b0);
            float v01 = tanhf(acc[mi][nj][1] + b1);
            float v10 = tanhf(acc[mi][nj][2] + b0);
            float v11 = tanhf(acc[mi][nj][3] + b1);
            size_t o0 = (size_t)row * 512 + n0 + cl;
            *reinterpret_cast<__half2*>(O + o0) =
                __halves2half2(__float2half_rn(v00), __float2half_rn(v01));
            *reinterpret_cast<__half2*>(O + o0 + 8 * 512) =
                __halves2half2(__float2half_rn(v10), __float2half_rn(v11));
        }
    } else {
        // stage W4^T slice [64 i][128 n] fp32 into dead stage-0 area
        float* sw4 = (float*)smem;
        for (int e = tid; e < 8192; e += 256) {
            int i = e >> 7, c = e & 127;
            sw4[i * 129 + c] = g_w4t[mlp][i * 512 + n0 + c];
        }
        __syncthreads();
        const int iA = (wm * 64 + grp) & 63;
        float ps[4][2];
#pragma unroll
        for (int mi = 0; mi < 4; ++mi) { ps[mi][0] = 0.f; ps[mi][1] = 0.f; }
#pragma unroll
        for (int mi = 0; mi < 4; ++mi)
#pragma unroll
        for (int nj = 0; nj < 4; ++nj) {
            int cl = wn * 32 + nj * 8 + q * 2;
            float b0 = sbias[cl], b1 = sbias[cl + 1];
            int i0 = (iA + mi * 16) & 63, i1 = (iA + mi * 16 + 8) & 63;
            ps[mi][0] += tanhf(acc[mi][nj][0] + b0) * sw4[i0 * 129 + cl]
                       + tanhf(acc[mi][nj][1] + b1) * sw4[i0 * 129 + cl + 1];
            ps[mi][1] += tanhf(acc[mi][nj][2] + b0) * sw4[i1 * 129 + cl]
                       + tanhf(acc[mi][nj][3] + b1) * sw4[i1 * 129 + cl + 1];
        }
        int slice = blockIdx.x * 4 + wn;
#pragma unroll
        for (int mi = 0; mi < 4; ++mi)
#pragma unroll
        for (int rh = 0; rh < 2; ++rh) {
            float v = ps[mi][rh];
            v += __shfl_xor_sync(0xffffffffu, v, 1);
            v += __shfl_xor_sync(0xffffffffu, v, 2);
            if (q == 0)
                g_part[slice][m0 + wm * 64 + mi * 16 + rh * 8 + grp] = v;
        }
    }
}

// ============================================================================
// gemm_l1: K=64, Z split 3-product. grid (4, 2048). Writes g_h1 (device sym).
// ============================================================================
__global__ __launch_bounds__(256, 2) void gemm_l1(
    const float* __restrict__ b1s, const float* __restrict__ b1t)
{
    extern __shared__ uint8_t smem[];
    const uint32_t sb = (uint32_t)__cvta_generic_to_shared(smem);
    const int tid = threadIdx.x, lane = tid & 31, wid = tid >> 5;
    const int wm = wid >> 2, wn = wid & 3;
    const int grp = lane >> 2, q = lane & 3;
    const int n0 = blockIdx.x * 128;
    const int mlp = (blockIdx.y >= 1024) ? 1 : 0;
    const int zrow0 = (blockIdx.y & 1023) * 128;
    const int m0 = blockIdx.y * 128;

    if (tid < 128)
        ((float*)(smem + 73728))[tid] = (mlp ? b1t : b1s)[n0 + tid];

#pragma unroll
    for (int i = 0; i < 8; i++) {
        int c = tid + i * 256;
        int hl = c >> 10, cc = c & 1023;
        int r = cc >> 3, kc = (cc & 7) << 3;
        const __half* src = (hl ? g_zl : g_zh) + (size_t)(zrow0 + r) * 64 + kc;
        CP16(sb + hl * 18432 + (r * 72 + kc) * 2, src);
    }
#pragma unroll
    for (int i = 0; i < 8; i++) {
        int c = tid + i * 256;
        int hl = c >> 10, cc = c & 1023;
        int n = cc >> 3, kc = (cc & 7) << 3;
        const __half* src = (hl ? g_w1l[mlp] : g_w1h[mlp]) + (size_t)(n0 + n) * 64 + kc;
        CP16(sb + 36864 + hl * 18432 + (n * 72 + kc) * 2, src);
    }
    CP_COMMIT; CP_WAIT(0);
    __syncthreads();

    float acc[4][4][4];
#pragma unroll
    for (int a = 0; a < 4; a++)
#pragma unroll
        for (int b = 0; b < 4; b++)
#pragma unroll
            for (int c = 0; c < 4; c++) acc[a][b][c] = 0.f;

    uint32_t offA[4], offB[2];
#pragma unroll
    for (int mi = 0; mi < 4; ++mi)
        offA[mi] = ((wm * 64 + mi * 16 + (lane & 15)) * 72 + (lane >> 4) * 8) * 2;
#pragma unroll
    for (int j = 0; j < 2; ++j)
        offB[j] = 36864 +
            ((wn * 32 + j * 16 + (lane & 7) + ((lane >> 4) << 3)) * 72 +
             ((lane >> 3) & 1) * 8) * 2;

#pragma unroll
    for (int ks = 0; ks < 64; ks += 16) {
        uint32_t ah[4][4], al[4][4];
#pragma unroll
        for (int mi = 0; mi < 4; ++mi) {
            LDSM4(ah[mi], sb + offA[mi] + ks * 2);
            LDSM4(al[mi], sb + 18432 + offA[mi] + ks * 2);
        }
#pragma unroll
        for (int j = 0; j < 2; ++j) {
            uint32_t bh[4], bl[4];
            LDSM4(bh, sb + offB[j] + ks * 2);
            LDSM4(bl, sb + 18432 + offB[j] + ks * 2);
#pragma unroll
            for (int mi = 0; mi < 4; ++mi) {
                MMA(acc[mi][j * 2],     ah[mi], bh[0], bh[1]);
                MMA(acc[mi][j * 2],     ah[mi], bl[0], bl[1]);
                MMA(acc[mi][j * 2],     al[mi], bh[0], bh[1]);
                MMA(acc[mi][j * 2 + 1], ah[mi], bh[2], bh[3]);
                MMA(acc[mi][j * 2 + 1], ah[mi], bl[2], bl[3]);
                MMA(acc[mi][j * 2 + 1], al[mi], bh[2], bh[3]);
            }
        }
    }

    const float* sbias = (const float*)(smem + 73728);
#pragma unroll
    for (int mi = 0; mi < 4; ++mi)
#pragma unroll
    for (int nj = 0; nj < 4; ++nj) {
        int row = m0 + wm * 64 + mi * 16 + grp;
        int cl  = wn * 32 + nj * 8 + q * 2;
        float b0 = sbias[cl], b1 = sbias[cl + 1];
        float v00 = tanhf(acc[mi][nj][0] + b0);
        float v01 = tanhf(acc[mi][nj][1] + b1);
        float v10 = tanhf(acc[mi][nj][2] + b0);
        float v11 = tanhf(acc[mi][nj][3] + b1);
        size_t o0 = (size_t)row * 512 + n0 + cl;
        *reinterpret_cast<__half2*>(g_h1 + o0) =
            __halves2half2(__float2half_rn(v00), __float2half_rn(v01));
        *reinterpret_cast<__half2*>(g_h1 + o0 + 8 * 512) =
            __halves2half2(__float2half_rn(v10), __float2half_rn(v11));
    }
}

// ============================================================================
__global__ __launch_bounds__(256) void final_k(
    const float* __restrict__ x, const float* __restrict__ sb4,
    const float* __restrict__ tb4, float* __restrict__ out)
{
    int r = blockIdx.x * 256 + threadIdx.x;
    int i = r & 63;
    float ds = sb4[i], dt = tb4[i];
#pragma unroll
    for (int s = 0; s < 16; s++) {
        ds += g_part[s][r];
        dt += g_part[s][HALF_M + r];
    }
    out[r] = (x[r] - dt) * expf(-ds);
}

// ============================================================================
extern "C" void kernel_launch(void* const* d_in, const int* in_sizes, int n_in,
                              void* d_out, int out_size)
{
    (void)in_sizes; (void)n_in; (void)out_size;
    const float* x    = (const float*)d_in[0];
    const float* koop = (const float*)d_in[1];
    const float* sW1 = (const float*)d_in[2];  const float* sb1 = (const float*)d_in[3];
    const float* sW2 = (const float*)d_in[4];  const float* sb2 = (const float*)d_in[5];
    const float* sW3 = (const float*)d_in[6];  const float* sb3 = (const float*)d_in[7];
    const float* sW4 = (const float*)d_in[8];  const float* sb4 = (const float*)d_in[9];
    const float* tW1 = (const float*)d_in[10]; const float* tb1 = (const float*)d_in[11];
    const float* tW2 = (const float*)d_in[12]; const float* tb2 = (const float*)d_in[13];
    const float* tW3 = (const float*)d_in[14]; const float* tb3 = (const float*)d_in[15];
    const float* tW4 = (const float*)d_in[16]; const float* tb4 = (const float*)d_in[17];
    float* out = (float*)d_out;

    static int done = 0;
    if (!done) {
        cudaFuncSetAttribute(gemm23, cudaFuncAttributeMaxDynamicSharedMemorySize, G23_SMEM);
        cudaFuncSetAttribute(gemm_l1, cudaFuncAttributeMaxDynamicSharedMemorySize, L1_SMEM);
        done = 1;
    }

    prep_z  <<<2048, 256>>>(koop);
    prep_w1 <<<dim3(2, 16, 2), dim3(32, 8)>>>(sW1, tW1);
    prep_w23<<<dim3(16, 16, 4), dim3(32, 8)>>>(sW2, sW3, tW2, tW3);
    prep_w4 <<<256, 256>>>(sW4, tW4);

    dim3 grid(4, 2048);
    gemm_l1<<<grid, 256, L1_SMEM>>>(sb1, tb1);
    gemm23 <<<grid, 256, G23_SMEM>>>(0, 0, sb2, tb2);
    gemm23 <<<grid, 256, G23_SMEM>>>(1, 1, sb3, tb3);
    final_k<<<512, 256>>>(x, sb4, tb4, out);
}

// round 10
// speedup vs baseline: 2.4300x; 1.4678x over previous
#include <cuda_runtime.h>
#include <cuda_fp16.h>
#include <math.h>
#include <stdint.h>

// ============================================================================
// Decoder_33208687133135 — Round 10: 1-product fp16 weights in layers 2/3.
// rows r (per MLP, 131072): Z[r][l] = koopman[r>>6][l][r&63]
// h1=tanh(Z W1+b1); h2=tanh(h1 W2+b2); h3=tanh(h2 W3+b3); diag=h3.W4[:,r&63]
// out = (x - dt) * exp(-ds)
// L1: Z split + W1 split, 3 products (exact input). L2/3: plain fp16 (1 prod).
// W4 diagonal fused into the layer-3 epilogue in fp32.
// ============================================================================

#define HALF_M 131072
#define MTOT   262144

// ---- static scratch --------------------------------------------------------
__device__ __half g_zh[(size_t)HALF_M * 64];
__device__ __half g_zl[(size_t)HALF_M * 64];
__device__ __half g_w1h[2][512 * 64];            // [mlp], W1^T [n][k]
__device__ __half g_w1l[2][512 * 64];
__device__ __half g_w23h[4][512 * 512];          // [mlp*2+layer], W^T [n][k] fp16
__device__ float  g_w4t[2][64 * 512];            // [mlp], W4^T [i][k]
__device__ __half g_h1[(size_t)MTOT * 512];
__device__ __half g_h2[(size_t)MTOT * 512];
__device__ float  g_part[16][MTOT];              // diag partials per 32-n slice

// ---- PTX helpers -----------------------------------------------------------
#define CP16(d, s) asm volatile("cp.async.cg.shared.global [%0], [%1], 16;" :: "r"(d), "l"(s))
#define CP_COMMIT  asm volatile("cp.async.commit_group;")
#define CP_WAIT(n) asm volatile("cp.async.wait_group %0;" :: "n"(n) : "memory")

#define LDSM4(R, addr)                                                         \
    asm volatile("ldmatrix.sync.aligned.m8n8.x4.shared.b16 {%0,%1,%2,%3}, [%4];" \
        : "=r"(R[0]), "=r"(R[1]), "=r"(R[2]), "=r"(R[3]) : "r"(addr))

#define MMA(d, a, b0, b1)                                                      \
    asm volatile("mma.sync.aligned.m16n8k16.row.col.f32.f16.f16.f32 "          \
        "{%0,%1,%2,%3},{%4,%5,%6,%7},{%8,%9},{%0,%1,%2,%3};"                   \
        : "+f"(d[0]), "+f"(d[1]), "+f"(d[2]), "+f"(d[3])                       \
        : "r"(a[0]), "r"(a[1]), "r"(a[2]), "r"(a[3]), "r"(b0), "r"(b1))

// ============================================================================
// prep kernels
// ============================================================================
__global__ __launch_bounds__(256) void prep_z(const float* __restrict__ koop)
{
    __shared__ float s[64][65];
    int b = blockIdx.x;
    const float* src = koop + (size_t)b * 4096;
    for (int e = threadIdx.x; e < 4096; e += 256) {
        int l = e >> 6, i = e & 63;
        s[i][l] = src[e];
    }
    __syncthreads();
    for (int e = threadIdx.x; e < 4096; e += 256) {
        int i = e >> 6, l = e & 63;
        float v = s[i][l];
        __half h = __float2half_rn(v);
        size_t o = (size_t)(b * 64 + i) * 64 + l;
        g_zh[o] = h;
        g_zl[o] = __float2half_rn(v - __half2float(h));
    }
}

__device__ __forceinline__ void tsp_tile2(const float* __restrict__ W, int K, int N,
                                          __half* __restrict__ oh, __half* __restrict__ ol)
{
    __shared__ float t[32][33];
    int tx = threadIdx.x, ty = threadIdx.y;
    int k0 = blockIdx.x * 32, n0 = blockIdx.y * 32;
#pragma unroll
    for (int j = 0; j < 4; j++)
        t[ty + j * 8][tx] = W[(size_t)(k0 + ty + j * 8) * N + n0 + tx];
    __syncthreads();
#pragma unroll
    for (int j = 0; j < 4; j++) {
        int n = n0 + ty + j * 8;
        float v = t[tx][ty + j * 8];
        __half h = __float2half_rn(v);
        size_t o = (size_t)n * K + k0 + tx;
        oh[o] = h;
        if (ol) ol[o] = __float2half_rn(v - __half2float(h));
    }
}

__global__ void prep_w1(const float* sW1, const float* tW1)
{
    int mlp = blockIdx.z;
    tsp_tile2(mlp ? tW1 : sW1, 64, 512, g_w1h[mlp], g_w1l[mlp]);
}

__global__ void prep_w23(const float* sW2, const float* sW3,
                         const float* tW2, const float* tW3)
{
    int z = blockIdx.z;   // mlp*2 + layer
    const float* W = (z == 0) ? sW2 : (z == 1) ? sW3 : (z == 2) ? tW2 : tW3;
    tsp_tile2(W, 512, 512, g_w23h[z], nullptr);
}

__global__ __launch_bounds__(256) void prep_w4(const float* sW4, const float* tW4)
{
    int e = blockIdx.x * 256 + threadIdx.x;   // 65536
    int mlp = e >> 15, rem = e & 32767;
    int i = rem >> 9, k = rem & 511;
    g_w4t[mlp][i * 512 + k] = (mlp ? tW4 : sW4)[(size_t)k * 64 + i];
}

// ============================================================================
// smem layouts (halves, stride 72)
// gemm23 stage: A[128][72] @0 (18432B), B[128][72] @18432 ; x2 stages
// ============================================================================
#define ST_BYTES 36864
#define B_OFF    18432
#define G23_BIAS (2 * ST_BYTES)
#define G23_SMEM (2 * ST_BYTES + 512)
// gemm_l1: Ah @0, Al @18432, Bh @36864, Bl @55296, bias @73728
#define L1_SMEM  74240

__device__ __forceinline__ void frag_offsets(int lane, int wm, int wn,
                                             uint32_t offA[4], uint32_t offB[2])
{
#pragma unroll
    for (int mi = 0; mi < 4; ++mi)
        offA[mi] = ((wm * 64 + mi * 16 + (lane & 15)) * 72 + (lane >> 4) * 8) * 2;
#pragma unroll
    for (int j = 0; j < 2; ++j)
        offB[j] = B_OFF +
            ((wn * 32 + j * 16 + (lane & 7) + ((lane >> 4) << 3)) * 72 +
             ((lane >> 3) & 1) * 8) * 2;
}

// 1-product compute of one 64-deep stage (acts fp16, weights fp16)
__device__ __forceinline__ void compute1(uint32_t cur, const uint32_t offA[4],
                                         const uint32_t offB[2], float (&acc)[4][4][4])
{
#pragma unroll
    for (int ks = 0; ks < 64; ks += 16) {
        uint32_t a[4][4];
#pragma unroll
        for (int mi = 0; mi < 4; ++mi) LDSM4(a[mi], cur + offA[mi] + ks * 2);
#pragma unroll
        for (int j = 0; j < 2; ++j) {
            uint32_t b[4];
            LDSM4(b, cur + offB[j] + ks * 2);
#pragma unroll
            for (int mi = 0; mi < 4; ++mi) {
                MMA(acc[mi][j * 2],     a[mi], b[0], b[1]);
                MMA(acc[mi][j * 2 + 1], a[mi], b[2], b[3]);
            }
        }
    }
}

// ============================================================================
// gemm23: C = tanh(A @ W^T + b). A/O selected inside (device symbols).
// grid (4 nCTA, 2048 mCTA), 256 threads, warp tile 64x32, 2 CTAs/SM.
// ============================================================================
__global__ __launch_bounds__(256, 2) void gemm23(
    int layer, int is_l3,
    const float* __restrict__ bias_s, const float* __restrict__ bias_t)
{
    extern __shared__ uint8_t smem[];
    const uint32_t sb = (uint32_t)__cvta_generic_to_shared(smem);
    const int tid = threadIdx.x, lane = tid & 31, wid = tid >> 5;
    const int wm = wid >> 2, wn = wid & 3;        // 2 x 4 warps
    const int grp = lane >> 2, q = lane & 3;
    const int n0 = blockIdx.x * 128;
    const int m0 = blockIdx.y * 128;
    const int mlp = (blockIdx.y >= 1024) ? 1 : 0;
    const __half* A  = layer ? g_h2 : g_h1;
    __half* O        = g_h2;                      // only used when !is_l3
    const __half* Wh = g_w23h[mlp * 2 + layer];

    if (tid < 128)
        ((float*)(smem + G23_BIAS))[tid] = (mlp ? bias_t : bias_s)[n0 + tid];

    auto load_stage = [&](uint32_t base, int k0) {
#pragma unroll
        for (int i = 0; i < 4; i++) {
            int c = tid + i * 256;
            int r = c >> 3, kc = (c & 7) << 3;
            CP16(base + (r * 72 + kc) * 2, A + (size_t)(m0 + r) * 512 + k0 + kc);
        }
#pragma unroll
        for (int i = 0; i < 4; i++) {
            int c = tid + i * 256;
            int n = c >> 3, kc = (c & 7) << 3;
            CP16(base + B_OFF + (n * 72 + kc) * 2,
                 Wh + (size_t)(n0 + n) * 512 + k0 + kc);
        }
        CP_COMMIT;
    };

    float acc[4][4][4];
#pragma unroll
    for (int a = 0; a < 4; a++)
#pragma unroll
        for (int b = 0; b < 4; b++)
#pragma unroll
            for (int c = 0; c < 4; c++) acc[a][b][c] = 0.f;

    uint32_t offA[4], offB[2];
    frag_offsets(lane, wm, wn, offA, offB);

    load_stage(sb, 0);
    for (int s = 0; s < 8; ++s) {
        if (s < 7) { load_stage(sb + ((s + 1) & 1) * ST_BYTES, (s + 1) * 64); CP_WAIT(1); }
        else       { CP_WAIT(0); }
        __syncthreads();
        compute1(sb + (s & 1) * ST_BYTES, offA, offB, acc);
        __syncthreads();
    }

    const float* sbias = (const float*)(smem + G23_BIAS);
    if (!is_l3) {
#pragma unroll
        for (int mi = 0; mi < 4; ++mi)
#pragma unroll
        for (int nj = 0; nj < 4; ++nj) {
            int row = m0 + wm * 64 + mi * 16 + grp;
            int cl  = wn * 32 + nj * 8 + q * 2;
            float b0 = sbias[cl], b1 = sbias[cl + 1];
            float v00 = tanhf(acc[mi][nj][0] + b0);
            float v01 = tanhf(acc[mi][nj][1] + b1);
            float v10 = tanhf(acc[mi][nj][2] + b0);
            float v11 = tanhf(acc[mi][nj][3] + b1);
            size_t o0 = (size_t)row * 512 + n0 + cl;
            *reinterpret_cast<__half2*>(O + o0) =
                __halves2half2(__float2half_rn(v00), __float2half_rn(v01));
            *reinterpret_cast<__half2*>(O + o0 + 8 * 512) =
                __halves2half2(__float2half_rn(v10), __float2half_rn(v11));
        }
    } else {
        // stage W4^T slice [64 i][128 n] fp32 into dead stage-0 area (33KB)
        float* sw4 = (float*)smem;
        for (int e = tid; e < 8192; e += 256) {
            int i = e >> 7, c = e & 127;
            sw4[i * 129 + c] = g_w4t[mlp][i * 512 + n0 + c];
        }
        __syncthreads();
        const int iA = (wm * 64 + grp) & 63;
        float ps[4][2];
#pragma unroll
        for (int mi = 0; mi < 4; ++mi) { ps[mi][0] = 0.f; ps[mi][1] = 0.f; }
#pragma unroll
        for (int mi = 0; mi < 4; ++mi)
#pragma unroll
        for (int nj = 0; nj < 4; ++nj) {
            int cl = wn * 32 + nj * 8 + q * 2;
            float b0 = sbias[cl], b1 = sbias[cl + 1];
            int i0 = (iA + mi * 16) & 63, i1 = (iA + mi * 16 + 8) & 63;
            ps[mi][0] += tanhf(acc[mi][nj][0] + b0) * sw4[i0 * 129 + cl]
                       + tanhf(acc[mi][nj][1] + b1) * sw4[i0 * 129 + cl + 1];
            ps[mi][1] += tanhf(acc[mi][nj][2] + b0) * sw4[i1 * 129 + cl]
                       + tanhf(acc[mi][nj][3] + b1) * sw4[i1 * 129 + cl + 1];
        }
        int slice = blockIdx.x * 4 + wn;
#pragma unroll
        for (int mi = 0; mi < 4; ++mi)
#pragma unroll
        for (int rh = 0; rh < 2; ++rh) {
            float v = ps[mi][rh];
            v += __shfl_xor_sync(0xffffffffu, v, 1);
            v += __shfl_xor_sync(0xffffffffu, v, 2);
            if (q == 0)
                g_part[slice][m0 + wm * 64 + mi * 16 + rh * 8 + grp] = v;
        }
    }
}

// ============================================================================
// gemm_l1: K=64, Z split + W1 split, 3 products (exact). grid (4, 2048).
// ============================================================================
__global__ __launch_bounds__(256, 2) void gemm_l1(
    const float* __restrict__ b1s, const float* __restrict__ b1t)
{
    extern __shared__ uint8_t smem[];
    const uint32_t sb = (uint32_t)__cvta_generic_to_shared(smem);
    const int tid = threadIdx.x, lane = tid & 31, wid = tid >> 5;
    const int wm = wid >> 2, wn = wid & 3;
    const int grp = lane >> 2, q = lane & 3;
    const int n0 = blockIdx.x * 128;
    const int mlp = (blockIdx.y >= 1024) ? 1 : 0;
    const int zrow0 = (blockIdx.y & 1023) * 128;
    const int m0 = blockIdx.y * 128;

    if (tid < 128)
        ((float*)(smem + 73728))[tid] = (mlp ? b1t : b1s)[n0 + tid];

#pragma unroll
    for (int i = 0; i < 8; i++) {
        int c = tid + i * 256;
        int hl = c >> 10, cc = c & 1023;
        int r = cc >> 3, kc = (cc & 7) << 3;
        const __half* src = (hl ? g_zl : g_zh) + (size_t)(zrow0 + r) * 64 + kc;
        CP16(sb + hl * 18432 + (r * 72 + kc) * 2, src);
    }
#pragma unroll
    for (int i = 0; i < 8; i++) {
        int c = tid + i * 256;
        int hl = c >> 10, cc = c & 1023;
        int n = cc >> 3, kc = (cc & 7) << 3;
        const __half* src = (hl ? g_w1l[mlp] : g_w1h[mlp]) + (size_t)(n0 + n) * 64 + kc;
        CP16(sb + 36864 + hl * 18432 + (n * 72 + kc) * 2, src);
    }
    CP_COMMIT; CP_WAIT(0);
    __syncthreads();

    float acc[4][4][4];
#pragma unroll
    for (int a = 0; a < 4; a++)
#pragma unroll
        for (int b = 0; b < 4; b++)
#pragma unroll
            for (int c = 0; c < 4; c++) acc[a][b][c] = 0.f;

    uint32_t offA[4], offB[2];
#pragma unroll
    for (int mi = 0; mi < 4; ++mi)
        offA[mi] = ((wm * 64 + mi * 16 + (lane & 15)) * 72 + (lane >> 4) * 8) * 2;
#pragma unroll
    for (int j = 0; j < 2; ++j)
        offB[j] = 36864 +
            ((wn * 32 + j * 16 + (lane & 7) + ((lane >> 4) << 3)) * 72 +
             ((lane >> 3) & 1) * 8) * 2;

#pragma unroll
    for (int ks = 0; ks < 64; ks += 16) {
        uint32_t ah[4][4], al[4][4];
#pragma unroll
        for (int mi = 0; mi < 4; ++mi) {
            LDSM4(ah[mi], sb + offA[mi] + ks * 2);
            LDSM4(al[mi], sb + 18432 + offA[mi] + ks * 2);
        }
#pragma unroll
        for (int j = 0; j < 2; ++j) {
            uint32_t bh[4], bl[4];
            LDSM4(bh, sb + offB[j] + ks * 2);
            LDSM4(bl, sb + 18432 + offB[j] + ks * 2);
#pragma unroll
            for (int mi = 0; mi < 4; ++mi) {
                MMA(acc[mi][j * 2],     ah[mi], bh[0], bh[1]);
                MMA(acc[mi][j * 2],     ah[mi], bl[0], bl[1]);
                MMA(acc[mi][j * 2],     al[mi], bh[0], bh[1]);
                MMA(acc[mi][j * 2 + 1], ah[mi], bh[2], bh[3]);
                MMA(acc[mi][j * 2 + 1], ah[mi], bl[2], bl[3]);
                MMA(acc[mi][j * 2 + 1], al[mi], bh[2], bh[3]);
            }
        }
    }

    const float* sbias = (const float*)(smem + 73728);
#pragma unroll
    for (int mi = 0; mi < 4; ++mi)
#pragma unroll
    for (int nj = 0; nj < 4; ++nj) {
        int row = m0 + wm * 64 + mi * 16 + grp;
        int cl  = wn * 32 + nj * 8 + q * 2;
        float b0 = sbias[cl], b1 = sbias[cl + 1];
        float v00 = tanhf(acc[mi][nj][0] + b0);
        float v01 = tanhf(acc[mi][nj][1] + b1);
        float v10 = tanhf(acc[mi][nj][2] + b0);
        float v11 = tanhf(acc[mi][nj][3] + b1);
        size_t o0 = (size_t)row * 512 + n0 + cl;
        *reinterpret_cast<__half2*>(g_h1 + o0) =
            __halves2half2(__float2half_rn(v00), __float2half_rn(v01));
        *reinterpret_cast<__half2*>(g_h1 + o0 + 8 * 512) =
            __halves2half2(__float2half_rn(v10), __float2half_rn(v11));
    }
}

// ============================================================================
__global__ __launch_bounds__(256) void final_k(
    const float* __restrict__ x, const float* __restrict__ sb4,
    const float* __restrict__ tb4, float* __restrict__ out)
{
    int r = blockIdx.x * 256 + threadIdx.x;
    int i = r & 63;
    float ds = sb4[i], dt = tb4[i];
#pragma unroll
    for (int s = 0; s < 16; s++) {
        ds += g_part[s][r];
        dt += g_part[s][HALF_M + r];
    }
    out[r] = (x[r] - dt) * expf(-ds);
}

// ============================================================================
extern "C" void kernel_launch(void* const* d_in, const int* in_sizes, int n_in,
                              void* d_out, int out_size)
{
    (void)in_sizes; (void)n_in; (void)out_size;
    const float* x    = (const float*)d_in[0];
    const float* koop = (const float*)d_in[1];
    const float* sW1 = (const float*)d_in[2];  const float* sb1 = (const float*)d_in[3];
    const float* sW2 = (const float*)d_in[4];  const float* sb2 = (const float*)d_in[5];
    const float* sW3 = (const float*)d_in[6];  const float* sb3 = (const float*)d_in[7];
    const float* sW4 = (const float*)d_in[8];  const float* sb4 = (const float*)d_in[9];
    const float* tW1 = (const float*)d_in[10]; const float* tb1 = (const float*)d_in[11];
    const float* tW2 = (const float*)d_in[12]; const float* tb2 = (const float*)d_in[13];
    const float* tW3 = (const float*)d_in[14]; const float* tb3 = (const float*)d_in[15];
    const float* tW4 = (const float*)d_in[16]; const float* tb4 = (const float*)d_in[17];
    float* out = (float*)d_out;

    static int done = 0;
    if (!done) {
        cudaFuncSetAttribute(gemm23, cudaFuncAttributeMaxDynamicSharedMemorySize, G23_SMEM);
        cudaFuncSetAttribute(gemm_l1, cudaFuncAttributeMaxDynamicSharedMemorySize, L1_SMEM);
        done = 1;
    }

    prep_z  <<<2048, 256>>>(koop);
    prep_w1 <<<dim3(2, 16, 2), dim3(32, 8)>>>(sW1, tW1);
    prep_w23<<<dim3(16, 16, 4), dim3(32, 8)>>>(sW2, sW3, tW2, tW3);
    prep_w4 <<<256, 256>>>(sW4, tW4);

    dim3 grid(4, 2048);
    gemm_l1<<<grid, 256, L1_SMEM>>>(sb1, tb1);
    gemm23 <<<grid, 256, G23_SMEM>>>(0, 0, sb2, tb2);
    gemm23 <<<grid, 256, G23_SMEM>>>(1, 1, sb3, tb3);
    final_k<<<512, 256>>>(x, sb4, tb4, out);
}

// round 11
// speedup vs baseline: 2.4751x; 1.0186x over previous
#include <cuda_runtime.h>
#include <cuda_fp16.h>
#include <math.h>
#include <stdint.h>

// ============================================================================
// Decoder_33208687133135 — Round 11: 3-stage pipeline, merged preps,
// gemm_l1 2-product (Z split x W1 fp16).
// rows r (per MLP, 131072): Z[r][l] = koopman[r>>6][l][r&63]
// h1=tanh(Z W1+b1); h2=tanh(h1 W2+b2); h3=tanh(h2 W3+b3); diag=h3.W4[:,r&63]
// out = (x - dt) * exp(-ds)
// ============================================================================

#define HALF_M 131072
#define MTOT   262144

// ---- static scratch --------------------------------------------------------
__device__ __half g_zh[(size_t)HALF_M * 64];
__device__ __half g_zl[(size_t)HALF_M * 64];
__device__ __half g_w1h[2][512 * 64];            // [mlp], W1^T [n][k] fp16
__device__ __half g_w23h[4][512 * 512];          // [mlp*2+layer], W^T [n][k] fp16
__device__ float  g_w4t[2][64 * 512];            // [mlp], W4^T [i][k]
__device__ __half g_h1[(size_t)MTOT * 512];
__device__ __half g_h2[(size_t)MTOT * 512];
__device__ float  g_part[16][MTOT];              // diag partials per 32-n slice

// ---- PTX helpers -----------------------------------------------------------
#define CP16(d, s) asm volatile("cp.async.cg.shared.global [%0], [%1], 16;" :: "r"(d), "l"(s))
#define CP_COMMIT  asm volatile("cp.async.commit_group;")
#define CP_WAIT(n) asm volatile("cp.async.wait_group %0;" :: "n"(n) : "memory")

#define LDSM4(R, addr)                                                         \
    asm volatile("ldmatrix.sync.aligned.m8n8.x4.shared.b16 {%0,%1,%2,%3}, [%4];" \
        : "=r"(R[0]), "=r"(R[1]), "=r"(R[2]), "=r"(R[3]) : "r"(addr))

#define MMA(d, a, b0, b1)                                                      \
    asm volatile("mma.sync.aligned.m16n8k16.row.col.f32.f16.f16.f32 "          \
        "{%0,%1,%2,%3},{%4,%5,%6,%7},{%8,%9},{%0,%1,%2,%3};"                   \
        : "+f"(d[0]), "+f"(d[1]), "+f"(d[2]), "+f"(d[3])                       \
        : "r"(a[0]), "r"(a[1]), "r"(a[2]), "r"(a[3]), "r"(b0), "r"(b1))

// ============================================================================
// prep kernels (2 launches total)
// ============================================================================
__global__ __launch_bounds__(256) void prep_z(const float* __restrict__ koop)
{
    __shared__ float s[64][65];
    int b = blockIdx.x;
    const float* src = koop + (size_t)b * 4096;
    for (int e = threadIdx.x; e < 4096; e += 256) {
        int l = e >> 6, i = e & 63;
        s[i][l] = src[e];
    }
    __syncthreads();
    for (int e = threadIdx.x; e < 4096; e += 256) {
        int i = e >> 6, l = e & 63;
        float v = s[i][l];
        __half h = __float2half_rn(v);
        size_t o = (size_t)(b * 64 + i) * 64 + l;
        g_zh[o] = h;
        g_zl[o] = __float2half_rn(v - __half2float(h));
    }
}

__device__ __forceinline__ void tsp_tile(const float* __restrict__ W, int K, int N,
                                         __half* __restrict__ oh)
{
    __shared__ float t[32][33];
    int tx = threadIdx.x, ty = threadIdx.y;
    int k0 = blockIdx.x * 32, n0 = blockIdx.y * 32;
#pragma unroll
    for (int j = 0; j < 4; j++)
        t[ty + j * 8][tx] = W[(size_t)(k0 + ty + j * 8) * N + n0 + tx];
    __syncthreads();
#pragma unroll
    for (int j = 0; j < 4; j++) {
        int n = n0 + ty + j * 8;
        oh[(size_t)n * K + k0 + tx] = __float2half_rn(t[tx][ty + j * 8]);
    }
}

// z: 0..3 -> W2/W3 of each mlp (16x16 tiles); 4,5 -> W1 s/t; 6 -> W4 both.
__global__ void prep_w(const float* sW1, const float* sW2, const float* sW3,
                       const float* sW4, const float* tW1, const float* tW2,
                       const float* tW3, const float* tW4)
{
    int z = blockIdx.z;
    if (z < 4) {
        const float* W = (z == 0) ? sW2 : (z == 1) ? sW3 : (z == 2) ? tW2 : tW3;
        tsp_tile(W, 512, 512, g_w23h[z]);
    } else if (z < 6) {
        if (blockIdx.x >= 2) return;
        int mlp = z - 4;
        tsp_tile(mlp ? tW1 : sW1, 64, 512, g_w1h[mlp]);
    } else {
        int tid = threadIdx.y * 32 + threadIdx.x;
        int e = (blockIdx.y * 16 + blockIdx.x) * 256 + tid;   // 65536
        int mlp = e >> 15, rem = e & 32767;
        int i = rem >> 9, k = rem & 511;
        g_w4t[mlp][i * 512 + k] = (mlp ? tW4 : sW4)[(size_t)k * 64 + i];
    }
}

// ============================================================================
// smem layouts (halves, stride 72)
// gemm23 stage: A[128][72] @0 (18432B), B[128][72] @18432 ; x3 stages (ring)
// ============================================================================
#define ST_BYTES 36864
#define B_OFF    18432
#define G23_BIAS (3 * ST_BYTES)
#define G23_SMEM (3 * ST_BYTES + 512)
// gemm_l1: Ah @0, Al @18432, Bh @36864, bias @55296
#define L1_SMEM  55808

__device__ __forceinline__ void frag_offsets(int lane, int wm, int wn,
                                             uint32_t offA[4], uint32_t offB[2])
{
#pragma unroll
    for (int mi = 0; mi < 4; ++mi)
        offA[mi] = ((wm * 64 + mi * 16 + (lane & 15)) * 72 + (lane >> 4) * 8) * 2;
#pragma unroll
    for (int j = 0; j < 2; ++j)
        offB[j] = B_OFF +
            ((wn * 32 + j * 16 + (lane & 7) + ((lane >> 4) << 3)) * 72 +
             ((lane >> 3) & 1) * 8) * 2;
}

// 1-product compute of one 64-deep stage (acts fp16, weights fp16)
__device__ __forceinline__ void compute1(uint32_t cur, const uint32_t offA[4],
                                         const uint32_t offB[2], float (&acc)[4][4][4])
{
#pragma unroll
    for (int ks = 0; ks < 64; ks += 16) {
        uint32_t a[4][4];
#pragma unroll
        for (int mi = 0; mi < 4; ++mi) LDSM4(a[mi], cur + offA[mi] + ks * 2);
#pragma unroll
        for (int j = 0; j < 2; ++j) {
            uint32_t b[4];
            LDSM4(b, cur + offB[j] + ks * 2);
#pragma unroll
            for (int mi = 0; mi < 4; ++mi) {
                MMA(acc[mi][j * 2],     a[mi], b[0], b[1]);
                MMA(acc[mi][j * 2 + 1], a[mi], b[2], b[3]);
            }
        }
    }
}

// ============================================================================
// gemm23: C = tanh(A @ W^T + b). 3-stage cp.async ring, one sync per stage.
// grid (4 nCTA, 2048 mCTA), 256 threads, warp tile 64x32, 2 CTAs/SM.
// ============================================================================
__global__ __launch_bounds__(256, 2) void gemm23(
    int layer, int is_l3,
    const float* __restrict__ bias_s, const float* __restrict__ bias_t)
{
    extern __shared__ uint8_t smem[];
    const uint32_t sb = (uint32_t)__cvta_generic_to_shared(smem);
    const int tid = threadIdx.x, lane = tid & 31, wid = tid >> 5;
    const int wm = wid >> 2, wn = wid & 3;        // 2 x 4 warps
    const int grp = lane >> 2, q = lane & 3;
    const int n0 = blockIdx.x * 128;
    const int m0 = blockIdx.y * 128;
    const int mlp = (blockIdx.y >= 1024) ? 1 : 0;
    const __half* A  = layer ? g_h2 : g_h1;
    __half* O        = g_h2;                      // only used when !is_l3
    const __half* Wh = g_w23h[mlp * 2 + layer];

    if (tid < 128)
        ((float*)(smem + G23_BIAS))[tid] = (mlp ? bias_t : bias_s)[n0 + tid];

    auto load_stage = [&](uint32_t base, int k0) {
#pragma unroll
        for (int i = 0; i < 4; i++) {
            int c = tid + i * 256;
            int r = c >> 3, kc = (c & 7) << 3;
            CP16(base + (r * 72 + kc) * 2, A + (size_t)(m0 + r) * 512 + k0 + kc);
        }
#pragma unroll
        for (int i = 0; i < 4; i++) {
            int c = tid + i * 256;
            int n = c >> 3, kc = (c & 7) << 3;
            CP16(base + B_OFF + (n * 72 + kc) * 2,
                 Wh + (size_t)(n0 + n) * 512 + k0 + kc);
        }
        CP_COMMIT;
    };

    float acc[4][4][4];
#pragma unroll
    for (int a = 0; a < 4; a++)
#pragma unroll
        for (int b = 0; b < 4; b++)
#pragma unroll
            for (int c = 0; c < 4; c++) acc[a][b][c] = 0.f;

    uint32_t offA[4], offB[2];
    frag_offsets(lane, wm, wn, offA, offB);

    load_stage(sb, 0);
    load_stage(sb + ST_BYTES, 64);
#pragma unroll 1
    for (int s = 0; s < 8; ++s) {
        if (s < 7) CP_WAIT(1); else CP_WAIT(0);
        __syncthreads();
        if (s < 6) {
            int nb = (s + 2) % 3;
            load_stage(sb + nb * ST_BYTES, (s + 2) * 64);
        }
        compute1(sb + (s % 3) * ST_BYTES, offA, offB, acc);
    }
    __syncthreads();

    const float* sbias = (const float*)(smem + G23_BIAS);
    if (!is_l3) {
#pragma unroll
        for (int mi = 0; mi < 4; ++mi)
#pragma unroll
        for (int nj = 0; nj < 4; ++nj) {
            int row = m0 + wm * 64 + mi * 16 + grp;
            int cl  = wn * 32 + nj * 8 + q * 2;
            float b0 = sbias[cl], b1 = sbias[cl + 1];
            float v00 = tanhf(acc[mi][nj][0] + b0);
            float v01 = tanhf(acc[mi][nj][1] + b1);
            float v10 = tanhf(acc[mi][nj][2] + b0);
            float v11 = tanhf(acc[mi][nj][3] + b1);
            size_t o0 = (size_t)row * 512 + n0 + cl;
            *reinterpret_cast<__half2*>(O + o0) =
                __halves2half2(__float2half_rn(v00), __float2half_rn(v01));
            *reinterpret_cast<__half2*>(O + o0 + 8 * 512) =
                __halves2half2(__float2half_rn(v10), __float2half_rn(v11));
        }
    } else {
        // stage W4^T slice [64 i][128 n] fp32 into dead ring area (33KB)
        float* sw4 = (float*)smem;
        for (int e = tid; e < 8192; e += 256) {
            int i = e >> 7, c = e & 127;
            sw4[i * 129 + c] = g_w4t[mlp][i * 512 + n0 + c];
        }
        __syncthreads();
        const int iA = (wm * 64 + grp) & 63;
        float ps[4][2];
#pragma unroll
        for (int mi = 0; mi < 4; ++mi) { ps[mi][0] = 0.f; ps[mi][1] = 0.f; }
#pragma unroll
        for (int mi = 0; mi < 4; ++mi)
#pragma unroll
        for (int nj = 0; nj < 4; ++nj) {
            int cl = wn * 32 + nj * 8 + q * 2;
            float b0 = sbias[cl], b1 = sbias[cl + 1];
            int i0 = (iA + mi * 16) & 63, i1 = (iA + mi * 16 + 8) & 63;
            ps[mi][0] += tanhf(acc[mi][nj][0] + b0) * sw4[i0 * 129 + cl]
                       + tanhf(acc[mi][nj][1] + b1) * sw4[i0 * 129 + cl + 1];
            ps[mi][1] += tanhf(acc[mi][nj][2] + b0) * sw4[i1 * 129 + cl]
                       + tanhf(acc[mi][nj][3] + b1) * sw4[i1 * 129 + cl + 1];
        }
        int slice = blockIdx.x * 4 + wn;
#pragma unroll
        for (int mi = 0; mi < 4; ++mi)
#pragma unroll
        for (int rh = 0; rh < 2; ++rh) {
            float v = ps[mi][rh];
            v += __shfl_xor_sync(0xffffffffu, v, 1);
            v += __shfl_xor_sync(0xffffffffu, v, 2);
            if (q == 0)
                g_part[slice][m0 + wm * 64 + mi * 16 + rh * 8 + grp] = v;
        }
    }
}

// ============================================================================
// gemm_l1: K=64, Z split (2 products: Zh*W + Zl*W), W1 fp16. grid (4, 2048).
// ============================================================================
__global__ __launch_bounds__(256, 2) void gemm_l1(
    const float* __restrict__ b1s, const float* __restrict__ b1t)
{
    extern __shared__ uint8_t smem[];
    const uint32_t sb = (uint32_t)__cvta_generic_to_shared(smem);
    const int tid = threadIdx.x, lane = tid & 31, wid = tid >> 5;
    const int wm = wid >> 2, wn = wid & 3;
    const int grp = lane >> 2, q = lane & 3;
    const int n0 = blockIdx.x * 128;
    const int mlp = (blockIdx.y >= 1024) ? 1 : 0;
    const int zrow0 = (blockIdx.y & 1023) * 128;
    const int m0 = blockIdx.y * 128;

    if (tid < 128)
        ((float*)(smem + 55296))[tid] = (mlp ? b1t : b1s)[n0 + tid];

    // A: Zh @0, Zl @18432 (128 x 64 each)
#pragma unroll
    for (int i = 0; i < 8; i++) {
        int c = tid + i * 256;
        int hl = c >> 10, cc = c & 1023;
        int r = cc >> 3, kc = (cc & 7) << 3;
        const __half* src = (hl ? g_zl : g_zh) + (size_t)(zrow0 + r) * 64 + kc;
        CP16(sb + hl * 18432 + (r * 72 + kc) * 2, src);
    }
    // B: W1^T fp16 @36864 (128 n x 64 k)
#pragma unroll
    for (int i = 0; i < 4; i++) {
        int c = tid + i * 256;
        int n = c >> 3, kc = (c & 7) << 3;
        CP16(sb + 36864 + (n * 72 + kc) * 2,
             g_w1h[mlp] + (size_t)(n0 + n) * 64 + kc);
    }
    CP_COMMIT; CP_WAIT(0);
    __syncthreads();

    float acc[4][4][4];
#pragma unroll
    for (int a = 0; a < 4; a++)
#pragma unroll
        for (int b = 0; b < 4; b++)
#pragma unroll
            for (int c = 0; c < 4; c++) acc[a][b][c] = 0.f;

    uint32_t offA[4], offB[2];
#pragma unroll
    for (int mi = 0; mi < 4; ++mi)
        offA[mi] = ((wm * 64 + mi * 16 + (lane & 15)) * 72 + (lane >> 4) * 8) * 2;
#pragma unroll
    for (int j = 0; j < 2; ++j)
        offB[j] = 36864 +
            ((wn * 32 + j * 16 + (lane & 7) + ((lane >> 4) << 3)) * 72 +
             ((lane >> 3) & 1) * 8) * 2;

#pragma unroll
    for (int ks = 0; ks < 64; ks += 16) {
        uint32_t ah[4][4], al[4][4];
#pragma unroll
        for (int mi = 0; mi < 4; ++mi) {
            LDSM4(ah[mi], sb + offA[mi] + ks * 2);
            LDSM4(al[mi], sb + 18432 + offA[mi] + ks * 2);
        }
#pragma unroll
        for (int j = 0; j < 2; ++j) {
            uint32_t b[4];
            LDSM4(b, sb + offB[j] + ks * 2);
#pragma unroll
            for (int mi = 0; mi < 4; ++mi) {
                MMA(acc[mi][j * 2],     ah[mi], b[0], b[1]);
                MMA(acc[mi][j * 2],     al[mi], b[0], b[1]);
                MMA(acc[mi][j * 2 + 1], ah[mi], b[2], b[3]);
                MMA(acc[mi][j * 2 + 1], al[mi], b[2], b[3]);
            }
        }
    }

    const float* sbias = (const float*)(smem + 55296);
#pragma unroll
    for (int mi = 0; mi < 4; ++mi)
#pragma unroll
    for (int nj = 0; nj < 4; ++nj) {
        int row = m0 + wm * 64 + mi * 16 + grp;
        int cl  = wn * 32 + nj * 8 + q * 2;
        float b0 = sbias[cl], b1 = sbias[cl + 1];
        float v00 = tanhf(acc[mi][nj][0] + b0);
        float v01 = tanhf(acc[mi][nj][1] + b1);
        float v10 = tanhf(acc[mi][nj][2] + b0);
        float v11 = tanhf(acc[mi][nj][3] + b1);
        size_t o0 = (size_t)row * 512 + n0 + cl;
        *reinterpret_cast<__half2*>(g_h1 + o0) =
            __halves2half2(__float2half_rn(v00), __float2half_rn(v01));
        *reinterpret_cast<__half2*>(g_h1 + o0 + 8 * 512) =
            __halves2half2(__float2half_rn(v10), __float2half_rn(v11));
    }
}

// ============================================================================
__global__ __launch_bounds__(256) void final_k(
    const float* __restrict__ x, const float* __restrict__ sb4,
    const float* __restrict__ tb4, float* __restrict__ out)
{
    int r = blockIdx.x * 256 + threadIdx.x;
    int i = r & 63;
    float ds = sb4[i], dt = tb4[i];
#pragma unroll
    for (int s = 0; s < 16; s++) {
        ds += g_part[s][r];
        dt += g_part[s][HALF_M + r];
    }
    out[r] = (x[r] - dt) * expf(-ds);
}

// ============================================================================
extern "C" void kernel_launch(void* const* d_in, const int* in_sizes, int n_in,
                              void* d_out, int out_size)
{
    (void)in_sizes; (void)n_in; (void)out_size;
    const float* x    = (const float*)d_in[0];
    const float* koop = (const float*)d_in[1];
    const float* sW1 = (const float*)d_in[2];  const float* sb1 = (const float*)d_in[3];
    const float* sW2 = (const float*)d_in[4];  const float* sb2 = (const float*)d_in[5];
    const float* sW3 = (const float*)d_in[6];  const float* sb3 = (const float*)d_in[7];
    const float* sW4 = (const float*)d_in[8];  const float* sb4 = (const float*)d_in[9];
    const float* tW1 = (const float*)d_in[10]; const float* tb1 = (const float*)d_in[11];
    const float* tW2 = (const float*)d_in[12]; const float* tb2 = (const float*)d_in[13];
    const float* tW3 = (const float*)d_in[14]; const float* tb3 = (const float*)d_in[15];
    const float* tW4 = (const float*)d_in[16]; const float* tb4 = (const float*)d_in[17];
    float* out = (float*)d_out;

    static int done = 0;
    if (!done) {
        cudaFuncSetAttribute(gemm23, cudaFuncAttributeMaxDynamicSharedMemorySize, G23_SMEM);
        cudaFuncSetAttribute(gemm_l1, cudaFuncAttributeMaxDynamicSharedMemorySize, L1_SMEM);
        done = 1;
    }

    prep_z<<<2048, 256>>>(koop);
    prep_w<<<dim3(16, 16, 7), dim3(32, 8)>>>(sW1, sW2, sW3, sW4,
                                             tW1, tW2, tW3, tW4);

    dim3 grid(4, 2048);
    gemm_l1<<<grid, 256, L1_SMEM>>>(sb1, tb1);
    gemm23 <<<grid, 256, G23_SMEM>>>(0, 0, sb2, tb2);
    gemm23 <<<grid, 256, G23_SMEM>>>(1, 1, sb3, tb3);
    final_k<<<512, 256>>>(x, sb4, tb4, out);
}